// round 2
// baseline (speedup 1.0000x reference)
#include <cuda_runtime.h>
#include <cstdint>
#include <cstddef>

typedef unsigned long long ull;

// ---------- packed f32x2 helpers (Blackwell sm_103a) ----------
__device__ __forceinline__ ull pk2(float a, float b) {
    ull r; asm("mov.b64 %0, {%1, %2};" : "=l"(r) : "f"(a), "f"(b)); return r;
}
__device__ __forceinline__ float2 up2(ull v) {
    float2 f; asm("mov.b64 {%0, %1}, %2;" : "=f"(f.x), "=f"(f.y) : "l"(v)); return f;
}
__device__ __forceinline__ void fma2(ull& d, ull a, ull b) {
    asm("fma.rn.f32x2 %0, %1, %2, %0;" : "+l"(d) : "l"(a), "l"(b));
}
__device__ __forceinline__ void mul2(ull& d, ull a) {
    asm("mul.rn.f32x2 %0, %0, %1;" : "+l"(d) : "l"(a));
}

#define BN   4
#define CH   64
#define NPIX 4096   // 64*64

// ---------- scratch (no cudaMalloc allowed) ----------
__device__ float g_Q [BN*CH*NPIX];
__device__ float g_rk[BN*CH*NPIX];
__device__ float g_rv[BN*CH*NPIX];
__device__ float g_ik[BN*CH*NPIX];
__device__ float g_iv[BN*CH*NPIX];
__device__ float g_rr[BN*CH*NPIX];
__device__ float g_ir[BN*CH*NPIX];

// ============================================================
// conv3x3 + BN-affine + ReLU.  16x16 spatial tile, 16 out-chans
// per block, f32x2 register accumulation (8 packed pairs).
// grid: (4, 4, NCONV*B*4)  block: 256
// ============================================================
struct CArg { const float* inA; const float* inB; const float* w;
              const float* s; const float* bb; float* out; };
struct CPack { CArg c[4]; };

template<int CIN>
__global__ void __launch_bounds__(256) conv_k(CPack P) {
    __shared__ float tile[18*20];
    __shared__ float wsm[9*16];
    const int tid = threadIdx.x;
    const int tx = tid & 15, ty = tid >> 4;
    const int z = blockIdx.z;
    const int conv = z >> 4;
    const int b    = (z >> 2) & 3;
    const int ocb  = (z & 3) << 4;
    const CArg a = P.c[conv];
    const int ox0 = blockIdx.x << 4, oy0 = blockIdx.y << 4;
    const int ox = ox0 + tx, oy = oy0 + ty;

    ull acc[8];
#pragma unroll
    for (int p = 0; p < 8; p++) acc[p] = 0ull;

    for (int ci = 0; ci < CIN; ci++) {
        const float* src = a.inA; int cc = ci;
        if (CIN == 128 && ci >= 64) { src = a.inB; cc = ci - 64; }
        __syncthreads();
        const float* sp = src + ((size_t)b * 64 + cc) * 4096;
        for (int i = tid; i < 324; i += 256) {
            int r = i / 18, c2 = i - r * 18;
            int iy = oy0 - 1 + r, ix = ox0 - 1 + c2;
            float v = 0.f;
            if ((unsigned)iy < 64u && (unsigned)ix < 64u) v = sp[iy * 64 + ix];
            tile[r * 20 + c2] = v;
        }
        if (tid < 144) {
            int o = tid & 15, k = tid >> 4;
            wsm[k * 16 + o] = a.w[((size_t)(ocb + o) * CIN + ci) * 9 + k];
        }
        __syncthreads();

        float v[9];
#pragma unroll
        for (int ky = 0; ky < 3; ky++)
#pragma unroll
            for (int kx = 0; kx < 3; kx++)
                v[ky * 3 + kx] = tile[(ty + ky) * 20 + tx + kx];
#pragma unroll
        for (int k = 0; k < 9; k++) {
            ull vv = pk2(v[k], v[k]);
#pragma unroll
            for (int p = 0; p < 8; p++)
                fma2(acc[p], vv, *(const ull*)(wsm + k * 16 + 2 * p));
        }
    }

#pragma unroll
    for (int p = 0; p < 8; p++) {
        float2 o2 = up2(acc[p]);
#pragma unroll
        for (int j = 0; j < 2; j++) {
            int oc = ocb + 2 * p + j;
            float val = (j ? o2.y : o2.x) * a.s[oc] + a.bb[oc];
            val = fmaxf(val, 0.f);
            a.out[(((size_t)b * 64 + oc) * 64 + oy) * 64 + ox] = val;
        }
    }
}

// ============================================================
// Flash attention:  out[c,m] = sum_n softmax_n(Aq_m . Kq_n) V[c,n]
// 64-query tile per block, loop over 64 key tiles of 64.
// 256 threads, each owns a 4(m) x 4(c) f32x2-packed accumulator.
// grid: (64 mtiles, B, 2 attentions)  dyn smem 68352 B
// ============================================================
#define VP 68   // padded pitch for Vt / Pt (16B-aligned, conflict-light)

__global__ void __launch_bounds__(256) attn_k(const float* __restrict__ x,
                                              const float* __restrict__ y,
                                              const float* __restrict__ g1,
                                              const float* __restrict__ g2) {
    extern __shared__ float sm[];
    float* Qs  = sm;                 // [c][m]  64x64   (attn queries = conv K out)
    float* Ks  = Qs + 64 * 64;       // [c][n]  64x64   (attn keys    = conv Q out)
    float* Vt  = Ks + 64 * 64;       // [n][c]  64xVP
    float* Pt  = Vt + 64 * VP;       // [n][m]  64xVP   scores -> probs
    float* Mrow = Pt + 64 * VP;      // 64 running max
    float* Lrow = Mrow + 64;         // 64 running sum
    float* Srow = Lrow + 64;         // 64 per-iter rescale

    const int tid = threadIdx.x;
    const int tm = tid & 15, tn = tid >> 4;
    const int mt = blockIdx.x, b = blockIdx.y, a = blockIdx.z;
    const int m0 = mt * 64;

    const size_t boff = (size_t)b * CH * NPIX;
    const float* Aq  = (a ? g_ik : g_rk) + boff;
    const float* Av  = (a ? g_iv : g_rv) + boff;
    const float* Kq  = g_Q + boff;
    const float* res = (a ? x : y) + boff;
    float* outp      = (a ? g_ir : g_rr) + boff;
    const float gamma = a ? g2[0] : g1[0];

    // load query tile [c][m0..m0+63]
    for (int i = tid; i < 64 * 64; i += 256) {
        int c = i >> 6, mi = i & 63;
        Qs[i] = Aq[(size_t)c * NPIX + m0 + mi];
    }
    if (tid < 64) { Mrow[tid] = -1e30f; Lrow[tid] = 0.f; }

    ull O[4][2];
#pragma unroll
    for (int i = 0; i < 4; i++) { O[i][0] = 0ull; O[i][1] = 0ull; }
    __syncthreads();

    for (int nt = 0; nt < 64; nt++) {
        const int n0 = nt * 64;
        // load key tile [c][n] and V transposed [n][c]
        for (int i = tid; i < 64 * 64; i += 256) {
            int c = i >> 6, nn = i & 63;
            float kv = Kq[(size_t)c * NPIX + n0 + nn];
            float vv = Av[(size_t)c * NPIX + n0 + nn];
            Ks[i] = kv;
            Vt[nn * VP + c] = vv;
        }
        __syncthreads();

        // ---- S = Aq^T Kq  (4x4 per thread, f32x2 packed) ----
        ull S[4][2];
#pragma unroll
        for (int i = 0; i < 4; i++) { S[i][0] = 0ull; S[i][1] = 0ull; }
#pragma unroll 8
        for (int k = 0; k < 64; k++) {
            float4 q4 = *(const float4*)(Qs + k * 64 + tm * 4);
            ulonglong2 kk = *(const ulonglong2*)(Ks + k * 64 + tn * 4);
            ull q0 = pk2(q4.x, q4.x), q1 = pk2(q4.y, q4.y);
            ull q2 = pk2(q4.z, q4.z), q3 = pk2(q4.w, q4.w);
            fma2(S[0][0], q0, kk.x); fma2(S[0][1], q0, kk.y);
            fma2(S[1][0], q1, kk.x); fma2(S[1][1], q1, kk.y);
            fma2(S[2][0], q2, kk.x); fma2(S[2][1], q2, kk.y);
            fma2(S[3][0], q3, kk.x); fma2(S[3][1], q3, kk.y);
        }
        // write raw scores transposed: Pt[n][m]
#pragma unroll
        for (int i = 0; i < 4; i++) {
            float2 a0 = up2(S[i][0]), a1 = up2(S[i][1]);
            int m = tm * 4 + i;
            Pt[(tn * 4 + 0) * VP + m] = a0.x;
            Pt[(tn * 4 + 1) * VP + m] = a0.y;
            Pt[(tn * 4 + 2) * VP + m] = a1.x;
            Pt[(tn * 4 + 3) * VP + m] = a1.y;
        }
        __syncthreads();

        // ---- online softmax, warp w owns rows w*8..w*8+7 ----
        {
            const int lane = tid & 31, wrp = tid >> 5;
            for (int rr = 0; rr < 8; rr++) {
                int r = wrp * 8 + rr;
                float s0 = Pt[lane * VP + r];
                float s1 = Pt[(lane + 32) * VP + r];
                float mx = fmaxf(s0, s1);
#pragma unroll
                for (int o = 16; o > 0; o >>= 1)
                    mx = fmaxf(mx, __shfl_xor_sync(0xffffffffu, mx, o));
                float mold = Mrow[r];
                float mnew = fmaxf(mold, mx);
                float p0 = __expf(s0 - mnew), p1 = __expf(s1 - mnew);
                Pt[lane * VP + r] = p0;
                Pt[(lane + 32) * VP + r] = p1;
                float sum = p0 + p1;
#pragma unroll
                for (int o = 16; o > 0; o >>= 1)
                    sum += __shfl_xor_sync(0xffffffffu, sum, o);
                if (lane == 0) {
                    float sc = __expf(mold - mnew);
                    Lrow[r] = Lrow[r] * sc + sum;
                    Mrow[r] = mnew;
                    Srow[r] = sc;
                }
            }
        }
        __syncthreads();

        // ---- rescale accumulator, then O += P V^T ----
#pragma unroll
        for (int i = 0; i < 4; i++) {
            float sc = Srow[tm * 4 + i];
            ull s2 = pk2(sc, sc);
            mul2(O[i][0], s2); mul2(O[i][1], s2);
        }
#pragma unroll 4
        for (int n = 0; n < 64; n++) {
            float4 p4 = *(const float4*)(Pt + n * VP + tm * 4);
            ulonglong2 vv = *(const ulonglong2*)(Vt + n * VP + tn * 4);
            ull p0 = pk2(p4.x, p4.x), p1 = pk2(p4.y, p4.y);
            ull p2 = pk2(p4.z, p4.z), p3 = pk2(p4.w, p4.w);
            fma2(O[0][0], p0, vv.x); fma2(O[0][1], p0, vv.y);
            fma2(O[1][0], p1, vv.x); fma2(O[1][1], p1, vv.y);
            fma2(O[2][0], p2, vv.x); fma2(O[2][1], p2, vv.y);
            fma2(O[3][0], p3, vv.x); fma2(O[3][1], p3, vv.y);
        }
        __syncthreads();
    }

    // ---- epilogue: normalize, gamma-scale, residual add ----
#pragma unroll
    for (int i = 0; i < 4; i++) {
        int row = tm * 4 + i;
        float inv = 1.0f / Lrow[row];
        float2 a0 = up2(O[i][0]), a1 = up2(O[i][1]);
        float vals[4] = {a0.x, a0.y, a1.x, a1.y};
        int m = m0 + row;
#pragma unroll
        for (int j = 0; j < 4; j++) {
            size_t idx = (size_t)(tn * 4 + j) * NPIX + m;
            outp[idx] = gamma * (vals[j] * inv) + res[idx];
        }
    }
}

// ============================================================
// launch
// ============================================================
#define ATT_SMEM (size_t)((64*64*2 + 64*VP*2 + 64*3) * 4)

extern "C" void kernel_launch(void* const* d_in, const int* in_sizes, int n_in,
                              void* d_out, int out_size) {
    const float* x    = (const float*)d_in[0];
    const float* y    = (const float*)d_in[1];
    const float* q_w  = (const float*)d_in[2];
    const float* q_s  = (const float*)d_in[3];
    const float* q_b  = (const float*)d_in[4];
    const float* rk_w = (const float*)d_in[5];
    const float* rk_s = (const float*)d_in[6];
    const float* rk_b = (const float*)d_in[7];
    const float* rv_w = (const float*)d_in[8];
    const float* rv_s = (const float*)d_in[9];
    const float* rv_b = (const float*)d_in[10];
    const float* ik_w = (const float*)d_in[11];
    const float* ik_s = (const float*)d_in[12];
    const float* ik_b = (const float*)d_in[13];
    const float* iv_w = (const float*)d_in[14];
    const float* iv_s = (const float*)d_in[15];
    const float* iv_b = (const float*)d_in[16];
    const float* sr_w = (const float*)d_in[17];
    const float* sr_s = (const float*)d_in[18];
    const float* sr_b = (const float*)d_in[19];
    const float* g1   = (const float*)d_in[20];
    const float* g2   = (const float*)d_in[21];
    float* out = (float*)d_out;

    float *pQ, *prk, *prv, *pik, *piv, *prr, *pir;
    cudaGetSymbolAddress((void**)&pQ,  g_Q);
    cudaGetSymbolAddress((void**)&prk, g_rk);
    cudaGetSymbolAddress((void**)&prv, g_rv);
    cudaGetSymbolAddress((void**)&pik, g_ik);
    cudaGetSymbolAddress((void**)&piv, g_iv);
    cudaGetSymbolAddress((void**)&prr, g_rr);
    cudaGetSymbolAddress((void**)&pir, g_ir);

    cudaFuncSetAttribute(attn_k, cudaFuncAttributeMaxDynamicSharedMemorySize,
                         (int)ATT_SMEM);

    // 1) Q = conv(concat(x,y))
    CPack pq = {};
    pq.c[0] = { x, y, q_w, q_s, q_b, pQ };
    conv_k<128><<<dim3(4, 4, 16), 256>>>(pq);

    // 2) the four 64-channel K/V convs in one launch
    CPack pk = {};
    pk.c[0] = { x, nullptr, rk_w, rk_s, rk_b, prk };
    pk.c[1] = { x, nullptr, rv_w, rv_s, rv_b, prv };
    pk.c[2] = { y, nullptr, ik_w, ik_s, ik_b, pik };
    pk.c[3] = { y, nullptr, iv_w, iv_s, iv_b, piv };
    conv_k<64><<<dim3(4, 4, 64), 256>>>(pk);

    // 3) both attentions + gamma + residual
    attn_k<<<dim3(64, 4, 2), 256, ATT_SMEM>>>(x, y, g1, g2);

    // 4) out = conv(concat(rgb_refine, inf_refine))
    CPack ps = {};
    ps.c[0] = { prr, pir, sr_w, sr_s, sr_b, out };
    conv_k<128><<<dim3(4, 4, 16), 256>>>(ps);
}

// round 3
// speedup vs baseline: 1.0025x; 1.0025x over previous
#include <cuda_runtime.h>
#include <cstdint>
#include <cstddef>

typedef unsigned long long ull;

// ---------- packed f32x2 helpers (Blackwell sm_103a) ----------
__device__ __forceinline__ ull pk2(float a, float b) {
    ull r; asm("mov.b64 %0, {%1, %2};" : "=l"(r) : "f"(a), "f"(b)); return r;
}
__device__ __forceinline__ float2 up2(ull v) {
    float2 f; asm("mov.b64 {%0, %1}, %2;" : "=f"(f.x), "=f"(f.y) : "l"(v)); return f;
}
__device__ __forceinline__ void fma2(ull& d, ull a, ull b) {
    asm("fma.rn.f32x2 %0, %1, %2, %0;" : "+l"(d) : "l"(a), "l"(b));
}
__device__ __forceinline__ void mul2(ull& d, ull a) {
    asm("mul.rn.f32x2 %0, %0, %1;" : "+l"(d) : "l"(a));
}

#define BN   4
#define CH   64
#define NPIX 4096   // 64*64

// ---------- scratch (no cudaMalloc allowed) ----------
__device__ float g_Q [BN*CH*NPIX];
__device__ float g_rk[BN*CH*NPIX];
__device__ float g_rv[BN*CH*NPIX];
__device__ float g_ik[BN*CH*NPIX];
__device__ float g_iv[BN*CH*NPIX];
__device__ float g_rr[BN*CH*NPIX];
__device__ float g_ir[BN*CH*NPIX];

// ============================================================
// conv3x3 + BN-affine + ReLU.  16x16 spatial tile, 16 out-chans
// per block, f32x2 register accumulation (8 packed pairs).
// grid: (4, 4, NCONV*B*4)  block: 256
// ============================================================
struct CArg { const float* inA; const float* inB; const float* w;
              const float* s; const float* bb; float* out; };
struct CPack { CArg c[4]; };

template<int CIN>
__global__ void __launch_bounds__(256) conv_k(CPack P) {
    __shared__ float tile[18*20];
    __shared__ float wsm[9*16];
    const int tid = threadIdx.x;
    const int tx = tid & 15, ty = tid >> 4;
    const int z = blockIdx.z;
    const int conv = z >> 4;
    const int b    = (z >> 2) & 3;
    const int ocb  = (z & 3) << 4;
    const CArg a = P.c[conv];
    const int ox0 = blockIdx.x << 4, oy0 = blockIdx.y << 4;
    const int ox = ox0 + tx, oy = oy0 + ty;

    ull acc[8];
#pragma unroll
    for (int p = 0; p < 8; p++) acc[p] = 0ull;

    for (int ci = 0; ci < CIN; ci++) {
        const float* src = a.inA; int cc = ci;
        if (CIN == 128 && ci >= 64) { src = a.inB; cc = ci - 64; }
        __syncthreads();
        const float* sp = src + ((size_t)b * 64 + cc) * 4096;
        for (int i = tid; i < 324; i += 256) {
            int r = i / 18, c2 = i - r * 18;
            int iy = oy0 - 1 + r, ix = ox0 - 1 + c2;
            float v = 0.f;
            if ((unsigned)iy < 64u && (unsigned)ix < 64u) v = sp[iy * 64 + ix];
            tile[r * 20 + c2] = v;
        }
        if (tid < 144) {
            int o = tid & 15, k = tid >> 4;
            wsm[k * 16 + o] = a.w[((size_t)(ocb + o) * CIN + ci) * 9 + k];
        }
        __syncthreads();

        float v[9];
#pragma unroll
        for (int ky = 0; ky < 3; ky++)
#pragma unroll
            for (int kx = 0; kx < 3; kx++)
                v[ky * 3 + kx] = tile[(ty + ky) * 20 + tx + kx];
#pragma unroll
        for (int k = 0; k < 9; k++) {
            ull vv = pk2(v[k], v[k]);
#pragma unroll
            for (int p = 0; p < 8; p++)
                fma2(acc[p], vv, *(const ull*)(wsm + k * 16 + 2 * p));
        }
    }

#pragma unroll
    for (int p = 0; p < 8; p++) {
        float2 o2 = up2(acc[p]);
#pragma unroll
        for (int j = 0; j < 2; j++) {
            int oc = ocb + 2 * p + j;
            float val = (j ? o2.y : o2.x) * a.s[oc] + a.bb[oc];
            val = fmaxf(val, 0.f);
            a.out[(((size_t)b * 64 + oc) * 64 + oy) * 64 + ox] = val;
        }
    }
}

// ============================================================
// Flash attention:  out[c,m] = sum_n softmax_n(Aq_m . Kq_n) V[c,n]
// 64-query tile per block, loop over 64 key tiles of 64.
// 256 threads, each owns a 4(m) x 4(c) f32x2-packed accumulator.
// grid: (64 mtiles, B, 2 attentions)  dyn smem 68352 B
// ============================================================
#define VP 68   // padded pitch for Vt / Pt (16B-aligned, conflict-light)

__global__ void __launch_bounds__(256) attn_k(const float* __restrict__ x,
                                              const float* __restrict__ y,
                                              const float* __restrict__ g1,
                                              const float* __restrict__ g2) {
    extern __shared__ float sm[];
    float* Qs  = sm;                 // [c][m]  64x64   (attn queries = conv K out)
    float* Ks  = Qs + 64 * 64;       // [c][n]  64x64   (attn keys    = conv Q out)
    float* Vt  = Ks + 64 * 64;       // [n][c]  64xVP
    float* Pt  = Vt + 64 * VP;       // [n][m]  64xVP   scores -> probs
    float* Mrow = Pt + 64 * VP;      // 64 running max
    float* Lrow = Mrow + 64;         // 64 running sum
    float* Srow = Lrow + 64;         // 64 per-iter rescale

    const int tid = threadIdx.x;
    const int tm = tid & 15, tn = tid >> 4;
    const int mt = blockIdx.x, b = blockIdx.y, a = blockIdx.z;
    const int m0 = mt * 64;

    const size_t boff = (size_t)b * CH * NPIX;
    const float* Aq  = (a ? g_ik : g_rk) + boff;
    const float* Av  = (a ? g_iv : g_rv) + boff;
    const float* Kq  = g_Q + boff;
    const float* res = (a ? x : y) + boff;
    float* outp      = (a ? g_ir : g_rr) + boff;
    const float gamma = a ? g2[0] : g1[0];

    // load query tile [c][m0..m0+63]
    for (int i = tid; i < 64 * 64; i += 256) {
        int c = i >> 6, mi = i & 63;
        Qs[i] = Aq[(size_t)c * NPIX + m0 + mi];
    }
    if (tid < 64) { Mrow[tid] = -1e30f; Lrow[tid] = 0.f; }

    ull O[4][2];
#pragma unroll
    for (int i = 0; i < 4; i++) { O[i][0] = 0ull; O[i][1] = 0ull; }
    __syncthreads();

    for (int nt = 0; nt < 64; nt++) {
        const int n0 = nt * 64;
        // load key tile [c][n] and V transposed [n][c]
        for (int i = tid; i < 64 * 64; i += 256) {
            int c = i >> 6, nn = i & 63;
            float kv = Kq[(size_t)c * NPIX + n0 + nn];
            float vv = Av[(size_t)c * NPIX + n0 + nn];
            Ks[i] = kv;
            Vt[nn * VP + c] = vv;
        }
        __syncthreads();

        // ---- S = Aq^T Kq  (4x4 per thread, f32x2 packed) ----
        ull S[4][2];
#pragma unroll
        for (int i = 0; i < 4; i++) { S[i][0] = 0ull; S[i][1] = 0ull; }
#pragma unroll 8
        for (int k = 0; k < 64; k++) {
            float4 q4 = *(const float4*)(Qs + k * 64 + tm * 4);
            ulonglong2 kk = *(const ulonglong2*)(Ks + k * 64 + tn * 4);
            ull q0 = pk2(q4.x, q4.x), q1 = pk2(q4.y, q4.y);
            ull q2 = pk2(q4.z, q4.z), q3 = pk2(q4.w, q4.w);
            fma2(S[0][0], q0, kk.x); fma2(S[0][1], q0, kk.y);
            fma2(S[1][0], q1, kk.x); fma2(S[1][1], q1, kk.y);
            fma2(S[2][0], q2, kk.x); fma2(S[2][1], q2, kk.y);
            fma2(S[3][0], q3, kk.x); fma2(S[3][1], q3, kk.y);
        }
        // write raw scores transposed: Pt[n][m]
#pragma unroll
        for (int i = 0; i < 4; i++) {
            float2 a0 = up2(S[i][0]), a1 = up2(S[i][1]);
            int m = tm * 4 + i;
            Pt[(tn * 4 + 0) * VP + m] = a0.x;
            Pt[(tn * 4 + 1) * VP + m] = a0.y;
            Pt[(tn * 4 + 2) * VP + m] = a1.x;
            Pt[(tn * 4 + 3) * VP + m] = a1.y;
        }
        __syncthreads();

        // ---- online softmax, warp w owns rows w*8..w*8+7 ----
        {
            const int lane = tid & 31, wrp = tid >> 5;
            for (int rr = 0; rr < 8; rr++) {
                int r = wrp * 8 + rr;
                float s0 = Pt[lane * VP + r];
                float s1 = Pt[(lane + 32) * VP + r];
                float mx = fmaxf(s0, s1);
#pragma unroll
                for (int o = 16; o > 0; o >>= 1)
                    mx = fmaxf(mx, __shfl_xor_sync(0xffffffffu, mx, o));
                float mold = Mrow[r];
                float mnew = fmaxf(mold, mx);
                float p0 = __expf(s0 - mnew), p1 = __expf(s1 - mnew);
                Pt[lane * VP + r] = p0;
                Pt[(lane + 32) * VP + r] = p1;
                float sum = p0 + p1;
#pragma unroll
                for (int o = 16; o > 0; o >>= 1)
                    sum += __shfl_xor_sync(0xffffffffu, sum, o);
                if (lane == 0) {
                    float sc = __expf(mold - mnew);
                    Lrow[r] = Lrow[r] * sc + sum;
                    Mrow[r] = mnew;
                    Srow[r] = sc;
                }
            }
        }
        __syncthreads();

        // ---- rescale accumulator, then O += P V^T ----
#pragma unroll
        for (int i = 0; i < 4; i++) {
            float sc = Srow[tm * 4 + i];
            ull s2 = pk2(sc, sc);
            mul2(O[i][0], s2); mul2(O[i][1], s2);
        }
#pragma unroll 4
        for (int n = 0; n < 64; n++) {
            float4 p4 = *(const float4*)(Pt + n * VP + tm * 4);
            ulonglong2 vv = *(const ulonglong2*)(Vt + n * VP + tn * 4);
            ull p0 = pk2(p4.x, p4.x), p1 = pk2(p4.y, p4.y);
            ull p2 = pk2(p4.z, p4.z), p3 = pk2(p4.w, p4.w);
            fma2(O[0][0], p0, vv.x); fma2(O[0][1], p0, vv.y);
            fma2(O[1][0], p1, vv.x); fma2(O[1][1], p1, vv.y);
            fma2(O[2][0], p2, vv.x); fma2(O[2][1], p2, vv.y);
            fma2(O[3][0], p3, vv.x); fma2(O[3][1], p3, vv.y);
        }
        __syncthreads();
    }

    // ---- epilogue: normalize, gamma-scale, residual add ----
#pragma unroll
    for (int i = 0; i < 4; i++) {
        int row = tm * 4 + i;
        float inv = 1.0f / Lrow[row];
        float2 a0 = up2(O[i][0]), a1 = up2(O[i][1]);
        float vals[4] = {a0.x, a0.y, a1.x, a1.y};
        int m = m0 + row;
#pragma unroll
        for (int j = 0; j < 4; j++) {
            size_t idx = (size_t)(tn * 4 + j) * NPIX + m;
            outp[idx] = gamma * (vals[j] * inv) + res[idx];
        }
    }
}

// ============================================================
// launch
// ============================================================
#define ATT_SMEM (size_t)((64*64*2 + 64*VP*2 + 64*3) * 4)

extern "C" void kernel_launch(void* const* d_in, const int* in_sizes, int n_in,
                              void* d_out, int out_size) {
    const float* x    = (const float*)d_in[0];
    const float* y    = (const float*)d_in[1];
    const float* q_w  = (const float*)d_in[2];
    const float* q_s  = (const float*)d_in[3];
    const float* q_b  = (const float*)d_in[4];
    const float* rk_w = (const float*)d_in[5];
    const float* rk_s = (const float*)d_in[6];
    const float* rk_b = (const float*)d_in[7];
    const float* rv_w = (const float*)d_in[8];
    const float* rv_s = (const float*)d_in[9];
    const float* rv_b = (const float*)d_in[10];
    const float* ik_w = (const float*)d_in[11];
    const float* ik_s = (const float*)d_in[12];
    const float* ik_b = (const float*)d_in[13];
    const float* iv_w = (const float*)d_in[14];
    const float* iv_s = (const float*)d_in[15];
    const float* iv_b = (const float*)d_in[16];
    const float* sr_w = (const float*)d_in[17];
    const float* sr_s = (const float*)d_in[18];
    const float* sr_b = (const float*)d_in[19];
    const float* g1   = (const float*)d_in[20];
    const float* g2   = (const float*)d_in[21];
    float* out = (float*)d_out;

    float *pQ, *prk, *prv, *pik, *piv, *prr, *pir;
    cudaGetSymbolAddress((void**)&pQ,  g_Q);
    cudaGetSymbolAddress((void**)&prk, g_rk);
    cudaGetSymbolAddress((void**)&prv, g_rv);
    cudaGetSymbolAddress((void**)&pik, g_ik);
    cudaGetSymbolAddress((void**)&piv, g_iv);
    cudaGetSymbolAddress((void**)&prr, g_rr);
    cudaGetSymbolAddress((void**)&pir, g_ir);

    cudaFuncSetAttribute(attn_k, cudaFuncAttributeMaxDynamicSharedMemorySize,
                         (int)ATT_SMEM);

    // 1) Q = conv(concat(x,y))
    CPack pq = {};
    pq.c[0] = { x, y, q_w, q_s, q_b, pQ };
    conv_k<128><<<dim3(4, 4, 16), 256>>>(pq);

    // 2) the four 64-channel K/V convs in one launch
    CPack pk = {};
    pk.c[0] = { x, nullptr, rk_w, rk_s, rk_b, prk };
    pk.c[1] = { x, nullptr, rv_w, rv_s, rv_b, prv };
    pk.c[2] = { y, nullptr, ik_w, ik_s, ik_b, pik };
    pk.c[3] = { y, nullptr, iv_w, iv_s, iv_b, piv };
    conv_k<64><<<dim3(4, 4, 64), 256>>>(pk);

    // 3) both attentions + gamma + residual
    attn_k<<<dim3(64, 4, 2), 256, ATT_SMEM>>>(x, y, g1, g2);

    // 4) out = conv(concat(rgb_refine, inf_refine))
    CPack ps = {};
    ps.c[0] = { prr, pir, sr_w, sr_s, sr_b, out };
    conv_k<128><<<dim3(4, 4, 16), 256>>>(ps);
}